// round 7
// baseline (speedup 1.0000x reference)
#include <cuda_runtime.h>
#include <math.h>
#include <stdint.h>

#define B_SZ    2
#define L_SEQ   2048
#define D_MODEL 768
#define D_INNER 1536
#define D_STATE 16
#define DT_RANK 48
#define NK      (DT_RANK + 2*D_STATE)   /* 80 */
#define M_ROWS  (B_SZ*L_SEQ)            /* 4096 */

// ---------------- scratch (static device globals; no allocation) ----------------
__device__ float g_xz  [M_ROWS * 2 * D_INNER];
__device__ float g_xc  [2][M_ROWS * D_INNER];
__device__ float g_xd  [2][M_ROWS * NK];
__device__ float g_dt  [2][M_ROWS * D_INNER];
__device__ float g_y   [2][M_ROWS * D_INNER];
__device__ float g_gbuf[M_ROWS * D_INNER];

__device__ __forceinline__ float siluf(float x) {
    return x / (1.f + __expf(-x));
}
__device__ __forceinline__ float softplusf(float v) {
    return fmaxf(v, 0.f) + __logf(1.f + __expf(-fabsf(v)));
}

__device__ __forceinline__ void mma_bf16(float& c0, float& c1, float& c2, float& c3,
                                         uint32_t a0, uint32_t a1, uint32_t a2, uint32_t a3,
                                         uint32_t b0, uint32_t b1) {
    asm volatile("mma.sync.aligned.m16n8k16.row.col.f32.bf16.bf16.f32 "
                 "{%0,%1,%2,%3},{%4,%5,%6,%7},{%8,%9},{%0,%1,%2,%3};"
                 : "+f"(c0), "+f"(c1), "+f"(c2), "+f"(c3)
                 : "r"(a0), "r"(a1), "r"(a2), "r"(a3), "r"(b0), "r"(b1));
}

// pack two fp32 -> bf16x2 (lo half = x, hi half = y), RN
__device__ __forceinline__ uint32_t packbf(float x, float y) {
    uint32_t r;
    asm("cvt.rn.bf16x2.f32 %0, %1, %2;" : "=r"(r) : "f"(y), "f"(x));
    return r;
}
// hi/lo split of float4 along k: h0={k0,k1}, h1={k2,k3}; l* = residuals
__device__ __forceinline__ void split4(float4 v, uint32_t& h0, uint32_t& h1,
                                       uint32_t& l0, uint32_t& l1) {
    h0 = packbf(v.x, v.y);
    h1 = packbf(v.z, v.w);
    float hx = __uint_as_float(h0 << 16),  hy = __uint_as_float(h0 & 0xFFFF0000u);
    float hz = __uint_as_float(h1 << 16),  hw = __uint_as_float(h1 & 0xFFFF0000u);
    l0 = packbf(v.x - hx, v.y - hy);
    l1 = packbf(v.z - hz, v.w - hw);
}

// =====================================================================
// bf16x3 tensor-core NT GEMM: C[m,n] = act(sum_k A[m,k]*B[n,k] (+bias))
// BN=128, BK=16 (one m16n8k16 step per tile). 8 warps: wm{0,1} x wn{0..3},
// warp tile (BM/2)x32. Smem holds packed bf16x2 hi/lo tiles, XOR swizzle:
// k-pair c of row r stored at col (c+r)&7 (stride 8, conflict-free).
// gridDim.z selects branch. M%BM==0, K%16==0, N guarded (even).
// =====================================================================
template<int BM, int ACT>
__global__ void __launch_bounds__(256, 2)
gemm_bf16x3(const float* __restrict__ A, int lda, long sA,
            const float* __restrict__ B0, const float* __restrict__ B1, int ldb,
            const float* __restrict__ bias0, const float* __restrict__ bias1,
            float* __restrict__ C, int ldc, long sC,
            int N, int K)
{
    const float* B = B0;
    const float* bias = bias0;
    if (blockIdx.z) { B = B1; bias = bias1; A += sA; C += sC; }

    __shared__ uint32_t As_h[2][BM][8],  As_l[2][BM][8];
    __shared__ uint32_t Bs_h[2][128][8], Bs_l[2][128][8];

    constexpr int ITI = BM / 32;
    constexpr int ALD = BM / 64;

    const int tid  = threadIdx.x;
    const int lane = tid & 31;
    const int g    = lane >> 2;
    const int tg   = lane & 3;
    const int warp = tid >> 5;
    const int wm   = warp & 1;
    const int wn   = warp >> 1;

    const int blockRow = blockIdx.y * BM;
    const int blockCol = blockIdx.x * 128;

    const int fq = tid & 3;      // float4 index within k16
    const int fr = tid >> 2;     // row 0..63 (+64)

    const int ktiles = K / 16;

    const int n0 = blockCol + fr, n1 = n0 + 64;
    const float* Arow  = A + (size_t)(blockRow + fr) * lda + fq * 4;
    const float* Brow0 = B + (size_t)(n0 < N ? n0 : 0) * ldb + fq * 4;
    const float* Brow1 = B + (size_t)(n1 < N ? n1 : 0) * ldb + fq * 4;
    const bool   bok0 = (n0 < N), bok1 = (n1 < N);

    float4 pa[2], pb[2];
    // ---- prefetch tile 0 ----
    pa[0] = *(const float4*)(Arow);
    if (ALD == 2) pa[1] = *(const float4*)(Arow + (size_t)64 * lda);
    pb[0] = bok0 ? *(const float4*)(Brow0) : make_float4(0.f,0.f,0.f,0.f);
    pb[1] = bok1 ? *(const float4*)(Brow1) : make_float4(0.f,0.f,0.f,0.f);

    float acc[ITI][4][4];
    #pragma unroll
    for (int i = 0; i < ITI; ++i)
        #pragma unroll
        for (int j = 0; j < 4; ++j)
            #pragma unroll
            for (int r = 0; r < 4; ++r)
                acc[i][j][r] = 0.f;

    const int mwbase = wm * (BM/2);
    const int nwbase = wn * 32;
    const int c1 = (tg + g) & 7;        // swizzled col for k-pair tg   (rows ≡ g mod 8)
    const int c2 = (tg + g + 4) & 7;    // swizzled col for k-pair tg+4

    // swizzled store cols for filler
    const int sc0 = (2*fq + fr) & 7;
    const int sc1 = (2*fq + 1 + fr) & 7;

    for (int kt = 0; kt < ktiles; ++kt) {
        const int buf = kt & 1;

        // convert + store prefetched tile into smem[buf]
        {
            uint32_t h0,h1,l0,l1;
            split4(pa[0], h0,h1,l0,l1);
            As_h[buf][fr][sc0] = h0; As_h[buf][fr][sc1] = h1;
            As_l[buf][fr][sc0] = l0; As_l[buf][fr][sc1] = l1;
            if (ALD == 2) {
                split4(pa[1], h0,h1,l0,l1);
                As_h[buf][fr+64][sc0] = h0; As_h[buf][fr+64][sc1] = h1;
                As_l[buf][fr+64][sc0] = l0; As_l[buf][fr+64][sc1] = l1;
            }
            split4(pb[0], h0,h1,l0,l1);
            Bs_h[buf][fr][sc0] = h0; Bs_h[buf][fr][sc1] = h1;
            Bs_l[buf][fr][sc0] = l0; Bs_l[buf][fr][sc1] = l1;
            split4(pb[1], h0,h1,l0,l1);
            Bs_h[buf][fr+64][sc0] = h0; Bs_h[buf][fr+64][sc1] = h1;
            Bs_l[buf][fr+64][sc0] = l0; Bs_l[buf][fr+64][sc1] = l1;
        }
        __syncthreads();

        // prefetch next tile (latency hidden under compute)
        if (kt + 1 < ktiles) {
            int k0 = (kt + 1) * 16;
            pa[0] = *(const float4*)(Arow + k0);
            if (ALD == 2) pa[1] = *(const float4*)(Arow + (size_t)64 * lda + k0);
            pb[0] = bok0 ? *(const float4*)(Brow0 + k0) : make_float4(0.f,0.f,0.f,0.f);
            pb[1] = bok1 ? *(const float4*)(Brow1 + k0) : make_float4(0.f,0.f,0.f,0.f);
        }

        // B fragments (hi/lo)
        uint32_t bh0[4], bh1[4], bl0[4], bl1[4];
        #pragma unroll
        for (int j = 0; j < 4; ++j) {
            int rn = nwbase + j*8 + g;
            bh0[j] = Bs_h[buf][rn][c1]; bh1[j] = Bs_h[buf][rn][c2];
            bl0[j] = Bs_l[buf][rn][c1]; bl1[j] = Bs_l[buf][rn][c2];
        }
        #pragma unroll
        for (int i = 0; i < ITI; ++i) {
            int r0 = mwbase + i*16 + g, r1 = r0 + 8;
            uint32_t ah0 = As_h[buf][r0][c1], ah1 = As_h[buf][r1][c1];
            uint32_t ah2 = As_h[buf][r0][c2], ah3 = As_h[buf][r1][c2];
            uint32_t al0 = As_l[buf][r0][c1], al1 = As_l[buf][r1][c1];
            uint32_t al2 = As_l[buf][r0][c2], al3 = As_l[buf][r1][c2];
            #pragma unroll
            for (int j = 0; j < 4; ++j) {
                mma_bf16(acc[i][j][0], acc[i][j][1], acc[i][j][2], acc[i][j][3],
                         ah0, ah1, ah2, ah3, bh0[j], bh1[j]);
                mma_bf16(acc[i][j][0], acc[i][j][1], acc[i][j][2], acc[i][j][3],
                         ah0, ah1, ah2, ah3, bl0[j], bl1[j]);
                mma_bf16(acc[i][j][0], acc[i][j][1], acc[i][j][2], acc[i][j][3],
                         al0, al1, al2, al3, bh0[j], bh1[j]);
            }
        }
    }

    // ---- epilogue (paired float2 stores; N is even) ----
    #pragma unroll
    for (int i = 0; i < ITI; ++i) {
        int r0 = blockRow + mwbase + i*16 + g;
        int r1 = r0 + 8;
        #pragma unroll
        for (int j = 0; j < 4; ++j) {
            int c0 = blockCol + nwbase + j*8 + 2*tg;
            if (c0 < N) {
                float v00 = acc[i][j][0], v01 = acc[i][j][1];
                float v10 = acc[i][j][2], v11 = acc[i][j][3];
                if (ACT == 1) {
                    float bv0 = bias[c0], bv1 = bias[c0+1];
                    v00 = softplusf(v00 + bv0); v01 = softplusf(v01 + bv1);
                    v10 = softplusf(v10 + bv0); v11 = softplusf(v11 + bv1);
                }
                *(float2*)&C[(size_t)r0 * ldc + c0] = make_float2(v00, v01);
                *(float2*)&C[(size_t)r1 * ldc + c0] = make_float2(v10, v11);
            }
        }
    }
}

// ---------------- depthwise causal conv: 4 timesteps per thread ----------------
// grid (D_INNER/128, M_ROWS/4), block 128. Blocks never straddle batch boundary.
__global__ void conv_kernel(const float* __restrict__ cw_f, const float* __restrict__ cb_f,
                            const float* __restrict__ cw_b, const float* __restrict__ cb_b)
{
    int d  = blockIdx.x*128 + threadIdx.x;
    int m0 = blockIdx.y * 4;
    int b = m0 >> 11, t0 = m0 & (L_SEQ-1);

    float w0 = cw_f[d*4+0], w1 = cw_f[d*4+1], w2 = cw_f[d*4+2], w3 = cw_f[d*4+3];
    float v0 = cw_b[d*4+0], v1 = cw_b[d*4+1], v2 = cw_b[d*4+2], v3 = cw_b[d*4+3];
    float cbf = cb_f[d], cbb = cb_b[d];

    const float* xcol = g_xz + (size_t)(b*L_SEQ)*(2*D_INNER) + d;

    float xf[7], xb[7];
    #pragma unroll
    for (int k = 0; k < 7; ++k) {
        int u = t0 - 3 + k;
        xf[k] = (u >= 0) ? xcol[(size_t)u*(2*D_INNER)] : 0.f;
        xb[k] = (u >= 0) ? xcol[(size_t)(L_SEQ-1-u)*(2*D_INNER)] : 0.f;
    }

    float* o0 = &g_xc[0][(size_t)m0*D_INNER + d];
    float* o1 = &g_xc[1][(size_t)m0*D_INNER + d];
    #pragma unroll
    for (int q = 0; q < 4; ++q) {
        float af = cbf + w0*xf[q] + w1*xf[q+1] + w2*xf[q+2] + w3*xf[q+3];
        float ab = cbb + v0*xb[q] + v1*xb[q+1] + v2*xb[q+2] + v3*xb[q+3];
        o0[(size_t)q*D_INNER] = siluf(af);
        o1[(size_t)q*D_INNER] = siluf(ab);
    }
}

// ---------------- selective scan: 4 lanes/channel x 4 states/lane ----------------
__global__ void __launch_bounds__(64)
scan_kernel(const float* __restrict__ Alog_f, const float* __restrict__ Alog_b,
            const float* __restrict__ Dp_f,  const float* __restrict__ Dp_b)
{
    const int br = blockIdx.z;
    const float* __restrict__ dtbuf = br ? g_dt[1] : g_dt[0];
    const float* __restrict__ xcbuf = br ? g_xc[1] : g_xc[0];
    const float* __restrict__ xdbuf = br ? g_xd[1] : g_xd[0];
    float*       __restrict__ ybuf  = br ? g_y[1]  : g_y[0];
    const float* __restrict__ Alog  = br ? Alog_b : Alog_f;
    const float* __restrict__ Dpp   = br ? Dp_b   : Dp_f;

    const int tid  = threadIdx.x;
    const int s    = tid & 3;
    const int cloc = tid >> 2;
    const int d    = blockIdx.x*16 + cloc;
    const int b    = blockIdx.y;

    float Ac0 = -__expf(Alog[d*D_STATE + 4*s + 0]);
    float Ac1 = -__expf(Alog[d*D_STATE + 4*s + 1]);
    float Ac2 = -__expf(Alog[d*D_STATE + 4*s + 2]);
    float Ac3 = -__expf(Alog[d*D_STATE + 4*s + 3]);
    const float Dv = Dpp[d];

    const float* dtp = dtbuf + (size_t)b*L_SEQ*D_INNER + d;
    const float* xcp = xcbuf + (size_t)b*L_SEQ*D_INNER + d;
    const float4* Bp = (const float4*)(xdbuf + (size_t)b*L_SEQ*NK + DT_RANK + 4*s);
    const float4* Cp = (const float4*)(xdbuf + (size_t)b*L_SEQ*NK + DT_RANK + D_STATE + 4*s);
    const int rstride4 = NK / 4;

    float h0 = 0.f, h1 = 0.f, h2 = 0.f, h3 = 0.f;

    float  dt_c = __ldg(dtp);
    float  xv_c = __ldg(xcp);
    float4 B_c  = __ldg(Bp);
    float4 C_c  = __ldg(Cp);

    const long ystride = br ? -(long)D_INNER : (long)D_INNER;
    float* yp = ybuf + ((size_t)b*L_SEQ + (br ? (L_SEQ-1) : 0)) * D_INNER + d;

    for (int t = 0; t < L_SEQ; ++t) {
        float dt_n, xv_n; float4 B_n, C_n;
        if (t + 1 < L_SEQ) {
            dt_n = __ldg(dtp + (size_t)(t+1)*D_INNER);
            xv_n = __ldg(xcp + (size_t)(t+1)*D_INNER);
            B_n  = __ldg(Bp + (size_t)(t+1)*rstride4);
            C_n  = __ldg(Cp + (size_t)(t+1)*rstride4);
        }

        float dbx = dt_c * xv_c;
        h0 = __expf(dt_c * Ac0) * h0 + dbx * B_c.x;
        h1 = __expf(dt_c * Ac1) * h1 + dbx * B_c.y;
        h2 = __expf(dt_c * Ac2) * h2 + dbx * B_c.z;
        h3 = __expf(dt_c * Ac3) * h3 + dbx * B_c.w;

        float p = h0*C_c.x + h1*C_c.y + h2*C_c.z + h3*C_c.w;
        p += __shfl_xor_sync(0xffffffffu, p, 1);
        p += __shfl_xor_sync(0xffffffffu, p, 2);

        if (s == 0) *yp = p + Dv * xv_c;
        yp += ystride;

        dt_c = dt_n; xv_c = xv_n; B_c = B_n; C_c = C_n;
    }
}

// ---------------- combine: g = 0.5 * silu(z) * (y_f + y_b) ----------------
__global__ void combine_kernel()
{
    int idx = blockIdx.x*blockDim.x + threadIdx.x;
    int m = idx / D_INNER;
    int d = idx - m*D_INNER;
    float z = g_xz[(size_t)m*(2*D_INNER) + D_INNER + d];
    float s = siluf(z);
    g_gbuf[idx] = 0.5f * s * (g_y[0][idx] + g_y[1][idx]);
}

// ---------------- host ----------------
extern "C" void kernel_launch(void* const* d_in, const int* in_sizes, int n_in,
                              void* d_out, int out_size)
{
    const float* hs       = (const float*)d_in[0];
    const float* W_in     = (const float*)d_in[1];
    const float* conv_w   = (const float*)d_in[2];
    const float* conv_b   = (const float*)d_in[3];
    const float* conv_w_b = (const float*)d_in[4];
    const float* conv_b_b = (const float*)d_in[5];
    const float* W_x      = (const float*)d_in[6];
    const float* W_x_b    = (const float*)d_in[7];
    const float* W_dt     = (const float*)d_in[8];
    const float* b_dt     = (const float*)d_in[9];
    const float* W_dt_b   = (const float*)d_in[10];
    const float* b_dt_b   = (const float*)d_in[11];
    const float* A_log    = (const float*)d_in[12];
    const float* A_b_log  = (const float*)d_in[13];
    const float* Dp       = (const float*)d_in[14];
    const float* Dp_b     = (const float*)d_in[15];
    const float* W_out    = (const float*)d_in[16];
    float* out = (float*)d_out;

    static float *xz = nullptr, *xc = nullptr, *xd = nullptr, *dt = nullptr, *gb = nullptr;
    if (!xz) {
        cudaGetSymbolAddress((void**)&xz, g_xz);
        cudaGetSymbolAddress((void**)&xc, g_xc);
        cudaGetSymbolAddress((void**)&xd, g_xd);
        cudaGetSymbolAddress((void**)&dt, g_dt);
        cudaGetSymbolAddress((void**)&gb, g_gbuf);
    }
    const long sXC = (long)M_ROWS * D_INNER;
    const long sXD = (long)M_ROWS * NK;
    const long sDT = (long)M_ROWS * D_INNER;

    // 1) in-proj: (M=4096, N=3072, K=768)
    gemm_bf16x3<128,0><<<dim3(3072/128, M_ROWS/128, 1), 256>>>(
        hs, D_MODEL, 0, W_in, W_in, D_MODEL, nullptr, nullptr,
        xz, 2*D_INNER, 0, 2*D_INNER, D_MODEL);

    // 2) conv + silu (both branches)
    conv_kernel<<<dim3(D_INNER/128, M_ROWS/4), 128>>>(conv_w, conv_b, conv_w_b, conv_b_b);

    // 3) x_dbl both branches: (M=4096, N=80, K=1536), BM=64, grid.z=2
    gemm_bf16x3<64,0><<<dim3(1, M_ROWS/64, 2), 256>>>(
        xc, D_INNER, sXC, W_x, W_x_b, D_INNER, nullptr, nullptr,
        xd, NK, sXD, NK, D_INNER);

    // 4) dt both branches: softplus(dt_lo @ W_dt^T + b_dt)  (M=4096, N=1536, K=48)
    gemm_bf16x3<128,1><<<dim3(D_INNER/128, M_ROWS/128, 2), 256>>>(
        xd, NK, sXD, W_dt, W_dt_b, DT_RANK, b_dt, b_dt_b,
        dt, D_INNER, sDT, D_INNER, DT_RANK);

    // 5) selective scan, both branches
    scan_kernel<<<dim3(D_INNER/16, B_SZ, 2), 64>>>(A_log, A_b_log, Dp, Dp_b);

    // 6) combine with gate
    combine_kernel<<<(M_ROWS*D_INNER)/256, 256>>>();

    // 7) out-proj: (M=4096, N=768, K=1536)
    gemm_bf16x3<128,0><<<dim3(D_MODEL/128, M_ROWS/128, 1), 256>>>(
        gb, D_INNER, 0, W_out, W_out, D_INNER, nullptr, nullptr,
        out, D_MODEL, 0, D_MODEL, D_INNER);
}